// round 7
// baseline (speedup 1.0000x reference)
#include <cuda_runtime.h>
#include <cuda_bf16.h>
#include <cstdint>
#include <math.h>

typedef __nv_bfloat16 bf16;
typedef unsigned long long u64;

#define MBN   8
#define NQL   1024
#define NKVL  1024
#define HH    8
#define SCALE 0.125f
#define DD    512
#define N4    (MBN*NQL*DD)

__device__ bf16  g_xh[3][N4], g_xm[3][N4];
__device__ bf16  g_wh[4][DD*DD], g_wm[4][DD*DD];
__device__ bf16  g_qh[N4], g_qm[N4], g_kh[N4], g_km[N4];
__device__ float g_vf[N4];
__device__ bf16  g_vth[N4], g_vtm[N4];
__device__ bf16  g_cth[N4], g_ctm[N4];

// ---------------- helpers ----------------
__device__ __forceinline__ uint32_t smem_u32(const void* p){
    uint32_t a;
    asm("{ .reg .u64 t; cvta.to.shared.u64 t, %1; cvt.u32.u64 %0, t; }":"=r"(a):"l"(p));
    return a;
}
__device__ __forceinline__ void cp16(uint32_t s, const void* g){
    asm volatile("cp.async.cg.shared.global [%0], [%1], 16;"::"r"(s),"l"(g));
}
#define CP_COMMIT() asm volatile("cp.async.commit_group;":::"memory")

__device__ __forceinline__ void mma16816(float* c, const uint32_t* a,
                                         uint32_t b0, uint32_t b1){
    asm volatile(
      "mma.sync.aligned.m16n8k16.row.col.f32.bf16.bf16.f32 "
      "{%0,%1,%2,%3}, {%4,%5,%6,%7}, {%8,%9}, {%0,%1,%2,%3};"
      : "+f"(c[0]), "+f"(c[1]), "+f"(c[2]), "+f"(c[3])
      : "r"(a[0]), "r"(a[1]), "r"(a[2]), "r"(a[3]), "r"(b0), "r"(b1));
}
__device__ __forceinline__ void psplit2(float a, float b, uint32_t& h, uint32_t& m){
    bf16 ha = __float2bfloat16_rn(a), hb = __float2bfloat16_rn(b);
    bf16 ma = __float2bfloat16_rn(a - __bfloat162float(ha));
    bf16 mb = __float2bfloat16_rn(b - __bfloat162float(hb));
    __nv_bfloat162 H = __halves2bfloat162(ha, hb), M = __halves2bfloat162(ma, mb);
    h = *(uint32_t*)&H; m = *(uint32_t*)&M;
}
__device__ __forceinline__ u64 pack2(float a, float b){
    u64 r; asm("mov.b64 %0, {%1,%2};" : "=l"(r) : "f"(a), "f"(b)); return r;
}

// ---------------- input split ----------------
__global__ void xsplit(const float* __restrict__ x, bf16* __restrict__ xh,
                       bf16* __restrict__ xm){
    int i = (blockIdx.x*256 + threadIdx.x)*4;
    float4 v = *(const float4*)(x + i);
    uint32_t h0,m0,h1,m1;
    psplit2(v.x,v.y,h0,m0); psplit2(v.z,v.w,h1,m1);
    *(uint32_t*)(xh+i) = h0; *(uint32_t*)(xh+i+2) = h1;
    *(uint32_t*)(xm+i) = m0; *(uint32_t*)(xm+i+2) = m1;
}

// ---------------- W[k][n] -> split Wt[n][k] ----------------
__global__ void wtrans(const float* __restrict__ W, bf16* __restrict__ Wh,
                       bf16* __restrict__ Wm){
    __shared__ float t[32][33];
    int n0 = blockIdx.x*32, k0 = blockIdx.y*32;
    int tx = threadIdx.x, ty = threadIdx.y;
#pragma unroll
    for (int i=0;i<32;i+=8) t[ty+i][tx] = W[(size_t)(k0+ty+i)*DD + n0+tx];
    __syncthreads();
#pragma unroll
    for (int i=0;i<32;i+=8){
        float v = t[tx][ty+i];
        bf16 hh = __float2bfloat16_rn(v);
        size_t idx = (size_t)(n0+ty+i)*DD + k0+tx;
        Wh[idx] = hh;
        Wm[idx] = __float2bfloat16_rn(v - __bfloat162float(hh));
    }
}

// ---------------- V f32 -> split transposed ----------------
__global__ void vtrans(const float* __restrict__ V, bf16* __restrict__ Vh,
                       bf16* __restrict__ Vm){
    __shared__ float t[32][33];
    int z = blockIdx.z, m = z>>3, h = z&7;
    int kk0 = blockIdx.x*32, d0 = blockIdx.y*32;
    int tx = threadIdx.x, ty = threadIdx.y;
#pragma unroll
    for (int i=0;i<32;i+=8)
        t[ty+i][tx] = V[(size_t)(m*NKVL + kk0+ty+i)*DD + h*64 + d0+tx];
    __syncthreads();
#pragma unroll
    for (int i=0;i<32;i+=8){
        float v = t[tx][ty+i];
        bf16 hh = __float2bfloat16_rn(v);
        size_t idx = (size_t)(z*64 + d0+ty+i)*NKVL + kk0 + tx;
        Vh[idx] = hh;
        Vm[idx] = __float2bfloat16_rn(v - __bfloat162float(hh));
    }
}

// ---------------- GEMM: C = scale*(A @ Bt^T) + bias ----------------
#define PSTG 40960
#define PJ_SMEM (2*PSTG)

__global__ void __launch_bounds__(256) proj_bf(
    const bf16* __restrict__ Ah, const bf16* __restrict__ Am,
    const bf16* __restrict__ Bh, const bf16* __restrict__ Bm,
    const float* __restrict__ bias, float* __restrict__ Cf,
    bf16* __restrict__ Ch, bf16* __restrict__ Cm, float scale)
{
    extern __shared__ char sp[];
    uint32_t sb = smem_u32(sp);
    const int tid = threadIdx.x, lane = tid & 31, wid = tid >> 5;
    const int ln4 = lane >> 2, q2 = (lane & 3)*2;
    const int wm = (wid & 1)*64, wn = (wid >> 1)*32;
    const int bm = blockIdx.y*128, bn = blockIdx.x*128;
    float acc[4][4][4];
#pragma unroll
    for (int a=0;a<4;a++)
#pragma unroll
      for (int b=0;b<4;b++)
#pragma unroll
        for (int c=0;c<4;c++) acc[a][b][c]=0.f;

#define PJ_ISSUE(kt, s) do{ \
    uint32_t st = sb + (s)*PSTG; int k0 = (kt)*32; \
    for (int i = tid; i < 512; i += 256){ \
        int r = i>>2; uint32_t ro = r*80 + (i&3)*16; int c8 = (i&3)*8; \
        size_t ga = (size_t)(bm+r)*DD + k0 + c8; \
        cp16(st + ro,         Ah + ga); \
        cp16(st + 10240 + ro, Am + ga); \
        size_t gb = (size_t)(bn+r)*DD + k0 + c8; \
        cp16(st + 20480 + ro, Bh + gb); \
        cp16(st + 30720 + ro, Bm + gb); \
    } CP_COMMIT(); }while(0)

    PJ_ISSUE(0, 0);
#pragma unroll 1
    for (int kt = 0; kt < 16; kt++){
        if (kt < 15){
            PJ_ISSUE(kt+1, (kt+1)&1);
            asm volatile("cp.async.wait_group 1;":::"memory");
        } else {
            asm volatile("cp.async.wait_group 0;":::"memory");
        }
        __syncthreads();
        const bf16* sAh = (const bf16*)(sp + (kt&1)*PSTG);
        const bf16* sAm = sAh + 5120;
        const bf16* sBh = sAm + 5120;
        const bf16* sBm = sBh + 5120;
#pragma unroll
        for (int ks = 0; ks < 2; ks++){
            int kb = ks*16 + q2;
            uint32_t ah[4][4], am[4][4];
#pragma unroll
            for (int mi = 0; mi < 4; mi++){
                const bf16* p = sAh + (wm + mi*16 + ln4)*40 + kb;
                ah[mi][0]=*(const uint32_t*)p;     ah[mi][1]=*(const uint32_t*)(p+8*40);
                ah[mi][2]=*(const uint32_t*)(p+8); ah[mi][3]=*(const uint32_t*)(p+8*40+8);
                const bf16* pm = sAm + (wm + mi*16 + ln4)*40 + kb;
                am[mi][0]=*(const uint32_t*)pm;     am[mi][1]=*(const uint32_t*)(pm+8*40);
                am[mi][2]=*(const uint32_t*)(pm+8); am[mi][3]=*(const uint32_t*)(pm+8*40+8);
            }
#pragma unroll
            for (int nj = 0; nj < 4; nj++){
                const bf16* p = sBh + (wn + nj*8 + ln4)*40 + kb;
                uint32_t bh0 = *(const uint32_t*)p, bh1 = *(const uint32_t*)(p+8);
                const bf16* pm = sBm + (wn + nj*8 + ln4)*40 + kb;
                uint32_t bm0 = *(const uint32_t*)pm, bm1 = *(const uint32_t*)(pm+8);
#pragma unroll
                for (int mi = 0; mi < 4; mi++){
                    mma16816(acc[mi][nj], ah[mi], bh0, bh1);
                    mma16816(acc[mi][nj], ah[mi], bm0, bm1);
                    mma16816(acc[mi][nj], am[mi], bh0, bh1);
                }
            }
        }
        __syncthreads();
    }
#pragma unroll
    for (int mi = 0; mi < 4; mi++){
        int r0 = bm + wm + mi*16 + ln4;
#pragma unroll
        for (int nj = 0; nj < 4; nj++){
            int c = bn + wn + nj*8 + q2;
            float b0 = bias ? bias[c] : 0.f, b1 = bias ? bias[c+1] : 0.f;
            float v0 = acc[mi][nj][0]*scale + b0, v1 = acc[mi][nj][1]*scale + b1;
            float v2 = acc[mi][nj][2]*scale + b0, v3 = acc[mi][nj][3]*scale + b1;
            if (Cf){
                *(float2*)(Cf + (size_t)r0*DD + c)     = make_float2(v0, v1);
                *(float2*)(Cf + (size_t)(r0+8)*DD + c) = make_float2(v2, v3);
            } else {
                uint32_t h, m;
                psplit2(v0, v1, h, m);
                *(uint32_t*)(Ch + (size_t)r0*DD + c) = h;
                *(uint32_t*)(Cm + (size_t)r0*DD + c) = m;
                psplit2(v2, v3, h, m);
                *(uint32_t*)(Ch + (size_t)(r0+8)*DD + c) = h;
                *(uint32_t*)(Cm + (size_t)(r0+8)*DD + c) = m;
            }
        }
    }
}

// ---------------- fused attention ----------------
#define O_QH 0
#define O_QM 18432
#define O_KV 36864
#define KVSTG 36864
#define S_KH 0
#define S_KM 9216
#define S_VH 18432
#define S_VM 27648
#define O_HK (O_KV + 2*KVSTG)            // 2 x 64 x 16 float2 (negated dup) = 16384
#define O_V1 (O_HK + 16384)
#define AT_SMEM (O_V1 + 512)

__global__ void __launch_bounds__(256) attn_bf(
    const bf16* __restrict__ Qh_g, const bf16* __restrict__ Qm_g,
    const bf16* __restrict__ Kh_g, const bf16* __restrict__ Km_g,
    const bf16* __restrict__ Vh_g, const bf16* __restrict__ Vm_g,
    const float* __restrict__ Tq, const float* __restrict__ Tk,
    const float* __restrict__ kw1, const float* __restrict__ kb1,
    const float* __restrict__ kw2, const float* __restrict__ kb2,
    bf16* __restrict__ Cth, bf16* __restrict__ Ctm)
{
    extern __shared__ char sp[];
    uint32_t sb = smem_u32(sp);
    float2* HkD = (float2*)(sp + O_HK);   // [buf][key 64][j 16] = (-hv,-hv)
    float*  V1F = (float*)(sp + O_V1);    // [buf][key 64]

    const int tid = threadIdx.x, lane = tid & 31, wid = tid >> 5;
    const int ln4 = lane >> 2, q2 = (lane & 3)*2;
    const int m = blockIdx.z, h = blockIdx.y, q0 = blockIdx.x*128;
    const int rl0 = wid*16 + ln4;

    for (int i = tid; i < 1024; i += 256){
        int r = i>>3; uint32_t ro = r*144 + (i&7)*16;
        size_t g = (size_t)(m*NQL+q0+r)*DD + h*64 + (i&7)*8;
        cp16(sb + O_QH + ro, Qh_g + g);
        cp16(sb + O_QM + ro, Qm_g + g);
    }
#define KV_ISSUE(kk0, s) do{ \
    uint32_t st = sb + O_KV + (s)*KVSTG; \
    for (int i = tid; i < 512; i += 256){ \
        int r = i>>3; uint32_t ro = r*144 + (i&7)*16; int c8 = (i&7)*8; \
        size_t gk = (size_t)(m*NKVL + (kk0) + r)*DD + h*64 + c8; \
        cp16(st + S_KH + ro, Kh_g + gk); \
        cp16(st + S_KM + ro, Km_g + gk); \
        size_t gv = (size_t)((m*HH+h)*64 + r)*NKVL + (kk0) + c8; \
        cp16(st + S_VH + ro, Vh_g + gv); \
        cp16(st + S_VM + ro, Vm_g + gv); \
    } CP_COMMIT(); }while(0)

    KV_ISSUE(0, 0);

    // packed per-thread query-MLP state
    float ws[16];
    u64 uqp[16], wsp[16];
    float2 ta = *(const float2*)(Tq + (size_t)(m*NQL + q0 + rl0)*2);
    float2 tb = *(const float2*)(Tq + (size_t)(m*NQL + q0 + rl0 + 8)*2);
    float U1r0 = kb2[h] - 10.f, U1r1 = U1r0;
#pragma unroll
    for (int j = 0; j < 16; j++){
        ws[j] = 0.5f*kw2[j*HH + h];
        float w0 = kw1[j], w1 = kw1[16+j], b = kb1[j];
        float u0 = ta.x*w0 + ta.y*w1 + b;
        float u1 = tb.x*w0 + tb.y*w1 + b;
        U1r0 = fmaf(ws[j], u0, U1r0);
        U1r1 = fmaf(ws[j], u1, U1r1);
        uqp[j] = pack2(u0, u1);
        wsp[j] = pack2(ws[j], ws[j]);
    }
    if (tid < 64){  // Hk for tile 0 (negated, duplicated)
        float2 tk2 = *(const float2*)(Tk + (size_t)(m*NKVL + tid)*2);
        float v1 = 0.f;
#pragma unroll
        for (int j = 0; j < 16; j++){
            float hk = tk2.x*kw1[j] + tk2.y*kw1[16+j];
            HkD[tid*16 + j] = make_float2(-hk, -hk);
            v1 = fmaf(ws[j], hk, v1);
        }
        V1F[tid] = v1;
    }

    float oacc[8][4];
#pragma unroll
    for (int j=0;j<8;j++)
#pragma unroll
        for (int c=0;c<4;c++) oacc[j][c]=0.f;
    float l0 = 0.f, l1 = 0.f;

#pragma unroll 1
    for (int t = 0; t < 16; t++){
        if (t < 15){
            KV_ISSUE((t+1)*64, (t+1)&1);
            if (tid < 64){
                float2 tk2 = *(const float2*)(Tk + (size_t)(m*NKVL + (t+1)*64 + tid)*2);
                float v1 = 0.f;
                float2* Hb = HkD + ((t+1)&1)*1024;
#pragma unroll
                for (int j = 0; j < 16; j++){
                    float hk = tk2.x*kw1[j] + tk2.y*kw1[16+j];
                    Hb[tid*16 + j] = make_float2(-hk, -hk);
                    v1 = fmaf(ws[j], hk, v1);
                }
                V1F[((t+1)&1)*64 + tid] = v1;
            }
            asm volatile("cp.async.wait_group 1;":::"memory");
        } else {
            asm volatile("cp.async.wait_group 0;":::"memory");
        }
        __syncthreads();

        const bf16* Qh = (const bf16*)(sp + O_QH);
        const bf16* Qm = (const bf16*)(sp + O_QM);
        const char* st = sp + O_KV + (t&1)*KVSTG;
        const bf16* Kh = (const bf16*)(st + S_KH);
        const bf16* Km = (const bf16*)(st + S_KM);
        const bf16* Vh = (const bf16*)(st + S_VH);
        const bf16* Vm = (const bf16*)(st + S_VM);
        const float2* Hc = HkD + (t&1)*1024;
        const float*  Vc = V1F + (t&1)*64;

        float sacc[8][4];
#pragma unroll
        for (int j=0;j<8;j++)
#pragma unroll
            for (int c=0;c<4;c++) sacc[j][c]=0.f;
#pragma unroll
        for (int ks = 0; ks < 4; ks++){
            int kb = ks*16 + q2;
            uint32_t qa[4], qb[4];
            const bf16* p = Qh + rl0*72 + kb;
            qa[0]=*(const uint32_t*)p;     qa[1]=*(const uint32_t*)(p+8*72);
            qa[2]=*(const uint32_t*)(p+8); qa[3]=*(const uint32_t*)(p+8*72+8);
            const bf16* pm = Qm + rl0*72 + kb;
            qb[0]=*(const uint32_t*)pm;     qb[1]=*(const uint32_t*)(pm+8*72);
            qb[2]=*(const uint32_t*)(pm+8); qb[3]=*(const uint32_t*)(pm+8*72+8);
#pragma unroll
            for (int j = 0; j < 8; j++){
                const bf16* pk = Kh + (j*8 + ln4)*72 + kb;
                uint32_t bh0 = *(const uint32_t*)pk, bh1 = *(const uint32_t*)(pk+8);
                const bf16* pk2 = Km + (j*8 + ln4)*72 + kb;
                uint32_t bm0 = *(const uint32_t*)pk2, bm1 = *(const uint32_t*)(pk2+8);
                mma16816(sacc[j], qa, bh0, bh1);
                mma16816(sacc[j], qa, bm0, bm1);
                mma16816(sacc[j], qb, bh0, bh1);
            }
        }

        uint32_t pah[4][4], pam[4][4];
#pragma unroll
        for (int j = 0; j < 8; j++){
            float pe[4];
#pragma unroll
            for (int e = 0; e < 2; e++){
                int c = j*8 + q2 + e;
                const u64* hp = (const u64*)(Hc + c*16);
                float v1c = Vc[c];
                u64 sp2 = pack2(sacc[j][e] + U1r0 - v1c,
                                sacc[j][2+e] + U1r1 - v1c);
#pragma unroll
                for (int jj = 0; jj < 16; jj++){
                    u64 tt;
                    asm("add.rn.f32x2 %0, %1, %2;" : "=l"(tt) : "l"(uqp[jj]), "l"(hp[jj]));
                    tt &= 0x7FFFFFFF7FFFFFFFULL;
                    asm("fma.rn.f32x2 %0, %1, %2, %3;"
                        : "=l"(sp2) : "l"(wsp[jj]), "l"(tt), "l"(sp2));
                }
                float r0, r1;
                asm("mov.b64 {%0,%1}, %2;" : "=f"(r0), "=f"(r1) : "l"(sp2));
                float e0 = __expf(r0), e1 = __expf(r1);
                l0 += e0; l1 += e1;
                pe[e] = e0; pe[2+e] = e1;
            }
            int tt2 = j >> 1, base = (j & 1)*2;
            psplit2(pe[0], pe[1], pah[tt2][base],   pam[tt2][base]);
            psplit2(pe[2], pe[3], pah[tt2][base+1], pam[tt2][base+1]);
        }
#pragma unroll
        for (int tt = 0; tt < 4; tt++){
            int kb = tt*16 + q2;
#pragma unroll
            for (int j2 = 0; j2 < 8; j2++){
                const bf16* pv = Vh + (j2*8 + ln4)*72 + kb;
                uint32_t bh0 = *(const uint32_t*)pv, bh1 = *(const uint32_t*)(pv+8);
                const bf16* pv2 = Vm + (j2*8 + ln4)*72 + kb;
                uint32_t bm0 = *(const uint32_t*)pv2, bm1 = *(const uint32_t*)(pv2+8);
                mma16816(oacc[j2], pah[tt], bh0, bh1);
                mma16816(oacc[j2], pah[tt], bm0, bm1);
                mma16816(oacc[j2], pam[tt], bh0, bh1);
            }
        }
        __syncthreads();
    }

    l0 += __shfl_xor_sync(0xffffffffu, l0, 1);
    l0 += __shfl_xor_sync(0xffffffffu, l0, 2);
    l1 += __shfl_xor_sync(0xffffffffu, l1, 1);
    l1 += __shfl_xor_sync(0xffffffffu, l1, 2);
    float inv0 = 1.f/l0, inv1 = 1.f/l1;
    size_t o0 = (size_t)(m*NQL + q0 + rl0)*DD + h*64;
    size_t o1 = o0 + 8*DD;
#pragma unroll
    for (int j2 = 0; j2 < 8; j2++){
        int c = j2*8 + q2;
        uint32_t hh, mm;
        psplit2(oacc[j2][0]*inv0, oacc[j2][1]*inv0, hh, mm);
        *(uint32_t*)(Cth + o0 + c) = hh; *(uint32_t*)(Ctm + o0 + c) = mm;
        psplit2(oacc[j2][2]*inv1, oacc[j2][3]*inv1, hh, mm);
        *(uint32_t*)(Cth + o1 + c) = hh; *(uint32_t*)(Ctm + o1 + c) = mm;
    }
}

// ---------------- host launcher ----------------
extern "C" void kernel_launch(void* const* d_in, const int* in_sizes, int n_in,
                              void* d_out, int out_size)
{
    const float* xq    = (const float*)d_in[0];
    const float* xk    = (const float*)d_in[1];
    const float* xv    = (const float*)d_in[2];
    const float* tq    = (const float*)d_in[3];
    const float* tk    = (const float*)d_in[4];
    const float* w_q   = (const float*)d_in[5];
    const float* w_k   = (const float*)d_in[6];
    const float* w_v   = (const float*)d_in[7];
    const float* w_out = (const float*)d_in[8];
    const float* b_out = (const float*)d_in[9];
    const float* kw1   = (const float*)d_in[10];
    const float* kb1   = (const float*)d_in[11];
    const float* kw2   = (const float*)d_in[12];
    const float* kb2   = (const float*)d_in[13];
    float* out = (float*)d_out;

    bf16 *xh,*xm,*wh,*wm,*qh,*qm,*kh,*km,*vth,*vtm,*cth,*ctm;
    float *vf;
    cudaGetSymbolAddress((void**)&xh,  g_xh);
    cudaGetSymbolAddress((void**)&xm,  g_xm);
    cudaGetSymbolAddress((void**)&wh,  g_wh);
    cudaGetSymbolAddress((void**)&wm,  g_wm);
    cudaGetSymbolAddress((void**)&qh,  g_qh);
    cudaGetSymbolAddress((void**)&qm,  g_qm);
    cudaGetSymbolAddress((void**)&kh,  g_kh);
    cudaGetSymbolAddress((void**)&km,  g_km);
    cudaGetSymbolAddress((void**)&vf,  g_vf);
    cudaGetSymbolAddress((void**)&vth, g_vth);
    cudaGetSymbolAddress((void**)&vtm, g_vtm);
    cudaGetSymbolAddress((void**)&cth, g_cth);
    cudaGetSymbolAddress((void**)&ctm, g_ctm);

    cudaFuncSetAttribute(proj_bf, cudaFuncAttributeMaxDynamicSharedMemorySize, PJ_SMEM);
    cudaFuncSetAttribute(attn_bf, cudaFuncAttributeMaxDynamicSharedMemorySize, AT_SMEM);

    xsplit<<<N4/1024, 256>>>(xq, xh + 0*(size_t)N4, xm + 0*(size_t)N4);
    xsplit<<<N4/1024, 256>>>(xk, xh + 1*(size_t)N4, xm + 1*(size_t)N4);
    xsplit<<<N4/1024, 256>>>(xv, xh + 2*(size_t)N4, xm + 2*(size_t)N4);

    dim3 tg(16,16), tb(32,8);
    wtrans<<<tg,tb>>>(w_q,   wh + 0*DD*DD, wm + 0*DD*DD);
    wtrans<<<tg,tb>>>(w_k,   wh + 1*DD*DD, wm + 1*DD*DD);
    wtrans<<<tg,tb>>>(w_v,   wh + 2*DD*DD, wm + 2*DD*DD);
    wtrans<<<tg,tb>>>(w_out, wh + 3*DD*DD, wm + 3*DD*DD);

    dim3 gg(4, 64);
    proj_bf<<<gg,256,PJ_SMEM>>>(xh+0*(size_t)N4, xm+0*(size_t)N4,
                                wh+0*DD*DD, wm+0*DD*DD,
                                nullptr, nullptr, qh, qm, SCALE);
    proj_bf<<<gg,256,PJ_SMEM>>>(xh+1*(size_t)N4, xm+1*(size_t)N4,
                                wh+1*DD*DD, wm+1*DD*DD,
                                nullptr, nullptr, kh, km, 1.0f);
    proj_bf<<<gg,256,PJ_SMEM>>>(xh+2*(size_t)N4, xm+2*(size_t)N4,
                                wh+2*DD*DD, wm+2*DD*DD,
                                nullptr, vf, nullptr, nullptr, 1.0f);

    dim3 gv(32, 2, 64);
    vtrans<<<gv,tb>>>(vf, vth, vtm);

    dim3 ga(8, HH, MBN);
    attn_bf<<<ga,256,AT_SMEM>>>(qh, qm, kh, km, vth, vtm,
                                tq, tk, kw1, kb1, kw2, kb2, cth, ctm);

    proj_bf<<<gg,256,PJ_SMEM>>>(cth, ctm, wh+3*DD*DD, wm+3*DD*DD,
                                b_out, out, nullptr, nullptr, 1.0f);
}

// round 8
// speedup vs baseline: 1.9310x; 1.9310x over previous
#include <cuda_runtime.h>
#include <cuda_bf16.h>
#include <cstdint>
#include <math.h>

typedef __nv_bfloat16 bf16;

#define MBN   8
#define NQL   1024
#define NKVL  1024
#define HH    8
#define SCALE 0.125f
#define DD    512
#define N4    (MBN*NQL*DD)

__device__ bf16  g_xh[3][N4], g_xm[3][N4];
__device__ bf16  g_wh[4][DD*DD], g_wm[4][DD*DD];
__device__ bf16  g_qh[N4], g_qm[N4], g_kh[N4], g_km[N4];
__device__ float g_vf[N4];
__device__ bf16  g_vth[N4], g_vtm[N4];
__device__ bf16  g_cth[N4], g_ctm[N4];

// ---------------- helpers ----------------
__device__ __forceinline__ uint32_t smem_u32(const void* p){
    uint32_t a;
    asm("{ .reg .u64 t; cvta.to.shared.u64 t, %1; cvt.u32.u64 %0, t; }":"=r"(a):"l"(p));
    return a;
}
__device__ __forceinline__ void cp16(uint32_t s, const void* g){
    asm volatile("cp.async.cg.shared.global [%0], [%1], 16;"::"r"(s),"l"(g));
}
#define CP_COMMIT() asm volatile("cp.async.commit_group;":::"memory")

__device__ __forceinline__ void mma16816(float* c, const uint32_t* a,
                                         uint32_t b0, uint32_t b1){
    asm volatile(
      "mma.sync.aligned.m16n8k16.row.col.f32.bf16.bf16.f32 "
      "{%0,%1,%2,%3}, {%4,%5,%6,%7}, {%8,%9}, {%0,%1,%2,%3};"
      : "+f"(c[0]), "+f"(c[1]), "+f"(c[2]), "+f"(c[3])
      : "r"(a[0]), "r"(a[1]), "r"(a[2]), "r"(a[3]), "r"(b0), "r"(b1));
}
__device__ __forceinline__ void psplit2(float a, float b, uint32_t& h, uint32_t& m){
    bf16 ha = __float2bfloat16_rn(a), hb = __float2bfloat16_rn(b);
    bf16 ma = __float2bfloat16_rn(a - __bfloat162float(ha));
    bf16 mb = __float2bfloat16_rn(b - __bfloat162float(hb));
    __nv_bfloat162 H = __halves2bfloat162(ha, hb), M = __halves2bfloat162(ma, mb);
    h = *(uint32_t*)&H; m = *(uint32_t*)&M;
}

// ---------------- input split (3 inputs, one launch) ----------------
__global__ void xsplit3(const float* __restrict__ x0, const float* __restrict__ x1,
                        const float* __restrict__ x2,
                        bf16* __restrict__ xh, bf16* __restrict__ xm){
    int z = blockIdx.y;
    const float* x = (z == 0) ? x0 : (z == 1) ? x1 : x2;
    size_t base = (size_t)z * N4;
    int i = (blockIdx.x*256 + threadIdx.x)*4;
    float4 v = *(const float4*)(x + i);
    uint32_t h0,m0,h1,m1;
    psplit2(v.x,v.y,h0,m0); psplit2(v.z,v.w,h1,m1);
    *(uint32_t*)(xh+base+i) = h0; *(uint32_t*)(xh+base+i+2) = h1;
    *(uint32_t*)(xm+base+i) = m0; *(uint32_t*)(xm+base+i+2) = m1;
}

// ---------------- W[k][n] -> split Wt[n][k] (4 weights, one launch) --------
__global__ void wtrans4(const float* __restrict__ W0, const float* __restrict__ W1,
                        const float* __restrict__ W2, const float* __restrict__ W3,
                        bf16* __restrict__ Wh, bf16* __restrict__ Wm){
    int z = blockIdx.z;
    const float* W = (z==0)?W0:(z==1)?W1:(z==2)?W2:W3;
    bf16* wh = Wh + (size_t)z*DD*DD;
    bf16* wm = Wm + (size_t)z*DD*DD;
    __shared__ float t[32][33];
    int n0 = blockIdx.x*32, k0 = blockIdx.y*32;
    int tx = threadIdx.x, ty = threadIdx.y;
#pragma unroll
    for (int i=0;i<32;i+=8) t[ty+i][tx] = W[(size_t)(k0+ty+i)*DD + n0+tx];
    __syncthreads();
#pragma unroll
    for (int i=0;i<32;i+=8){
        float v = t[tx][ty+i];
        bf16 hh = __float2bfloat16_rn(v);
        size_t idx = (size_t)(n0+ty+i)*DD + k0+tx;
        wh[idx] = hh;
        wm[idx] = __float2bfloat16_rn(v - __bfloat162float(hh));
    }
}

// ---------------- V f32 -> split transposed ----------------
__global__ void vtrans(const float* __restrict__ V, bf16* __restrict__ Vh,
                       bf16* __restrict__ Vm){
    __shared__ float t[32][33];
    int z = blockIdx.z, m = z>>3, h = z&7;
    int kk0 = blockIdx.x*32, d0 = blockIdx.y*32;
    int tx = threadIdx.x, ty = threadIdx.y;
#pragma unroll
    for (int i=0;i<32;i+=8)
        t[ty+i][tx] = V[(size_t)(m*NKVL + kk0+ty+i)*DD + h*64 + d0+tx];
    __syncthreads();
#pragma unroll
    for (int i=0;i<32;i+=8){
        float v = t[tx][ty+i];
        bf16 hh = __float2bfloat16_rn(v);
        size_t idx = (size_t)(z*64 + d0+ty+i)*NKVL + kk0 + tx;
        Vh[idx] = hh;
        Vm[idx] = __float2bfloat16_rn(v - __bfloat162float(hh));
    }
}

// ---------------- GEMM core macro (body shared by both GEMM kernels) --------
#define PSTG 40960
#define PJ_SMEM (2*PSTG)

#define PJ_ISSUE(kt, s) do{ \
    uint32_t st = sb + (s)*PSTG; int k0 = (kt)*32; \
    for (int i = tid; i < 512; i += 256){ \
        int r = i>>2; uint32_t ro = r*80 + (i&3)*16; int c8 = (i&3)*8; \
        size_t ga = (size_t)(bm+r)*DD + k0 + c8; \
        cp16(st + ro,         Ah + ga); \
        cp16(st + 10240 + ro, Am + ga); \
        size_t gb = (size_t)(bn+r)*DD + k0 + c8; \
        cp16(st + 20480 + ro, Bh + gb); \
        cp16(st + 30720 + ro, Bm + gb); \
    } CP_COMMIT(); }while(0)

#define PJ_MAINLOOP() \
    PJ_ISSUE(0, 0); \
    _Pragma("unroll 1") \
    for (int kt = 0; kt < 16; kt++){ \
        if (kt < 15){ \
            PJ_ISSUE(kt+1, (kt+1)&1); \
            asm volatile("cp.async.wait_group 1;":::"memory"); \
        } else { \
            asm volatile("cp.async.wait_group 0;":::"memory"); \
        } \
        __syncthreads(); \
        const bf16* sAh = (const bf16*)(sp + (kt&1)*PSTG); \
        const bf16* sAm = sAh + 5120; \
        const bf16* sBh = sAm + 5120; \
        const bf16* sBm = sBh + 5120; \
        _Pragma("unroll") \
        for (int ks = 0; ks < 2; ks++){ \
            int kb = ks*16 + q2; \
            uint32_t ah[4][4], am[4][4]; \
            _Pragma("unroll") \
            for (int mi = 0; mi < 4; mi++){ \
                const bf16* p = sAh + (wm + mi*16 + ln4)*40 + kb; \
                ah[mi][0]=*(const uint32_t*)p;     ah[mi][1]=*(const uint32_t*)(p+8*40); \
                ah[mi][2]=*(const uint32_t*)(p+8); ah[mi][3]=*(const uint32_t*)(p+8*40+8); \
                const bf16* pm = sAm + (wm + mi*16 + ln4)*40 + kb; \
                am[mi][0]=*(const uint32_t*)pm;     am[mi][1]=*(const uint32_t*)(pm+8*40); \
                am[mi][2]=*(const uint32_t*)(pm+8); am[mi][3]=*(const uint32_t*)(pm+8*40+8); \
            } \
            _Pragma("unroll") \
            for (int nj = 0; nj < 4; nj++){ \
                const bf16* p = sBh + (wn + nj*8 + ln4)*40 + kb; \
                uint32_t bh0 = *(const uint32_t*)p, bh1 = *(const uint32_t*)(p+8); \
                const bf16* pm = sBm + (wn + nj*8 + ln4)*40 + kb; \
                uint32_t bm0 = *(const uint32_t*)pm, bm1 = *(const uint32_t*)(pm+8); \
                _Pragma("unroll") \
                for (int mi = 0; mi < 4; mi++){ \
                    mma16816(acc[mi][nj], ah[mi], bh0, bh1); \
                    mma16816(acc[mi][nj], ah[mi], bm0, bm1); \
                    mma16816(acc[mi][nj], am[mi], bh0, bh1); \
                } \
            } \
        } \
        __syncthreads(); \
    }

// ---------------- merged QKV projection (z = 0:Q 1:K 2:V) ----------------
__global__ void __launch_bounds__(256) qkv_proj(
    const bf16* __restrict__ Xh, const bf16* __restrict__ Xm,
    const bf16* __restrict__ Wh, const bf16* __restrict__ Wm,
    bf16* __restrict__ Qh, bf16* __restrict__ Qm,
    bf16* __restrict__ Kh, bf16* __restrict__ Km,
    float* __restrict__ Vf)
{
    extern __shared__ char sp[];
    uint32_t sb = smem_u32(sp);
    const int tid = threadIdx.x, lane = tid & 31, wid = tid >> 5;
    const int ln4 = lane >> 2, q2 = (lane & 3)*2;
    const int wm = (wid & 1)*64, wn = (wid >> 1)*32;
    const int bm = blockIdx.y*128, bn = blockIdx.x*128;
    const int z = blockIdx.z;
    const bf16* Ah = Xh + (size_t)z*N4;
    const bf16* Am = Xm + (size_t)z*N4;
    const bf16* Bh = Wh + (size_t)z*DD*DD;
    const bf16* Bm = Wm + (size_t)z*DD*DD;
    float acc[4][4][4];
#pragma unroll
    for (int a=0;a<4;a++)
#pragma unroll
      for (int b=0;b<4;b++)
#pragma unroll
        for (int c=0;c<4;c++) acc[a][b][c]=0.f;

    PJ_MAINLOOP();

    const float scale = (z == 0) ? SCALE : 1.0f;
#pragma unroll
    for (int mi = 0; mi < 4; mi++){
        int r0 = bm + wm + mi*16 + ln4;
#pragma unroll
        for (int nj = 0; nj < 4; nj++){
            int c = bn + wn + nj*8 + q2;
            float v0 = acc[mi][nj][0]*scale, v1 = acc[mi][nj][1]*scale;
            float v2 = acc[mi][nj][2]*scale, v3 = acc[mi][nj][3]*scale;
            if (z == 2){
                *(float2*)(Vf + (size_t)r0*DD + c)     = make_float2(v0, v1);
                *(float2*)(Vf + (size_t)(r0+8)*DD + c) = make_float2(v2, v3);
            } else {
                bf16* Ch = (z == 0) ? Qh : Kh;
                bf16* Cm = (z == 0) ? Qm : Km;
                uint32_t h, m;
                psplit2(v0, v1, h, m);
                *(uint32_t*)(Ch + (size_t)r0*DD + c) = h;
                *(uint32_t*)(Cm + (size_t)r0*DD + c) = m;
                psplit2(v2, v3, h, m);
                *(uint32_t*)(Ch + (size_t)(r0+8)*DD + c) = h;
                *(uint32_t*)(Cm + (size_t)(r0+8)*DD + c) = m;
            }
        }
    }
}

// ---------------- output projection ----------------
__global__ void __launch_bounds__(256) out_proj(
    const bf16* __restrict__ Ah, const bf16* __restrict__ Am,
    const bf16* __restrict__ Bh, const bf16* __restrict__ Bm,
    const float* __restrict__ bias, float* __restrict__ Cf)
{
    extern __shared__ char sp[];
    uint32_t sb = smem_u32(sp);
    const int tid = threadIdx.x, lane = tid & 31, wid = tid >> 5;
    const int ln4 = lane >> 2, q2 = (lane & 3)*2;
    const int wm = (wid & 1)*64, wn = (wid >> 1)*32;
    const int bm = blockIdx.y*128, bn = blockIdx.x*128;
    float acc[4][4][4];
#pragma unroll
    for (int a=0;a<4;a++)
#pragma unroll
      for (int b=0;b<4;b++)
#pragma unroll
        for (int c=0;c<4;c++) acc[a][b][c]=0.f;

    PJ_MAINLOOP();

#pragma unroll
    for (int mi = 0; mi < 4; mi++){
        int r0 = bm + wm + mi*16 + ln4;
#pragma unroll
        for (int nj = 0; nj < 4; nj++){
            int c = bn + wn + nj*8 + q2;
            float b0 = bias[c], b1 = bias[c+1];
            *(float2*)(Cf + (size_t)r0*DD + c) =
                make_float2(acc[mi][nj][0] + b0, acc[mi][nj][1] + b1);
            *(float2*)(Cf + (size_t)(r0+8)*DD + c) =
                make_float2(acc[mi][nj][2] + b0, acc[mi][nj][3] + b1);
        }
    }
}

// ---------------- fused attention: 3-stage pipeline ----------------
#define O_QH 0
#define O_QM 18432
#define O_KV 36864
#define KVSTG 36864
#define S_KH 0
#define S_KM 9216
#define S_VH 18432
#define S_VM 27648
#define O_HK (O_KV + 3*KVSTG)          // 3 stages x 64 keys x 20 floats
#define HKSTG 5120
#define O_V1 (O_HK + 3*HKSTG)          // 3 stages x 64 floats
#define AT_SMEM (O_V1 + 3*256)

__global__ void __launch_bounds__(256) attn_bf(
    const bf16* __restrict__ Qh_g, const bf16* __restrict__ Qm_g,
    const bf16* __restrict__ Kh_g, const bf16* __restrict__ Km_g,
    const bf16* __restrict__ Vh_g, const bf16* __restrict__ Vm_g,
    const float* __restrict__ Tq, const float* __restrict__ Tk,
    const float* __restrict__ kw1, const float* __restrict__ kb1,
    const float* __restrict__ kw2, const float* __restrict__ kb2,
    bf16* __restrict__ Cth, bf16* __restrict__ Ctm)
{
    extern __shared__ char sp[];
    uint32_t sb = smem_u32(sp);

    const int tid = threadIdx.x, lane = tid & 31, wid = tid >> 5;
    const int ln4 = lane >> 2, q2 = (lane & 3)*2;
    const int m = blockIdx.z, h = blockIdx.y, q0 = blockIdx.x*128;
    const int rl0 = wid*16 + ln4;

    for (int i = tid; i < 1024; i += 256){
        int r = i>>3; uint32_t ro = r*144 + (i&7)*16;
        size_t g = (size_t)(m*NQL+q0+r)*DD + h*64 + (i&7)*8;
        cp16(sb + O_QH + ro, Qh_g + g);
        cp16(sb + O_QM + ro, Qm_g + g);
    }
#define KV_ISSUE(kk0, s) do{ \
    uint32_t st = sb + O_KV + (s)*KVSTG; \
    for (int i = tid; i < 512; i += 256){ \
        int r = i>>3; uint32_t ro = r*144 + (i&7)*16; int c8 = (i&7)*8; \
        size_t gk = (size_t)(m*NKVL + (kk0) + r)*DD + h*64 + c8; \
        cp16(st + S_KH + ro, Kh_g + gk); \
        cp16(st + S_KM + ro, Km_g + gk); \
        size_t gv = (size_t)((m*HH+h)*64 + r)*NKVL + (kk0) + c8; \
        cp16(st + S_VH + ro, Vh_g + gv); \
        cp16(st + S_VM + ro, Vm_g + gv); \
    } CP_COMMIT(); }while(0)

#define HK_GEN(tile, s) do{ \
    if (tid < 64){ \
        float2 tk2 = *(const float2*)(Tk + (size_t)(m*NKVL + (tile)*64 + tid)*2); \
        float v1 = 0.f; \
        float* Hb = (float*)(sp + O_HK + (s)*HKSTG); \
        _Pragma("unroll") \
        for (int j = 0; j < 16; j++){ \
            float hk = tk2.x*kw1[j] + tk2.y*kw1[16+j]; \
            Hb[tid*20 + j] = hk; \
            v1 = fmaf(ws[j], hk, v1); \
        } \
        ((float*)(sp + O_V1))[(s)*64 + tid] = v1; \
    } }while(0)

    KV_ISSUE(0, 0);
    KV_ISSUE(64, 1);

    float ws[16], uq0[16], uq1[16];
    float2 ta = *(const float2*)(Tq + (size_t)(m*NQL + q0 + rl0)*2);
    float2 tb = *(const float2*)(Tq + (size_t)(m*NQL + q0 + rl0 + 8)*2);
    float U1r0 = kb2[h] - 10.f, U1r1 = U1r0;
#pragma unroll
    for (int j = 0; j < 16; j++){
        ws[j] = 0.5f*kw2[j*HH + h];
        float w0 = kw1[j], w1 = kw1[16+j], b = kb1[j];
        uq0[j] = ta.x*w0 + ta.y*w1 + b;
        uq1[j] = tb.x*w0 + tb.y*w1 + b;
        U1r0 = fmaf(ws[j], uq0[j], U1r0);
        U1r1 = fmaf(ws[j], uq1[j], U1r1);
    }
    HK_GEN(0, 0);
    HK_GEN(1, 1);

    float oacc[8][4];
#pragma unroll
    for (int j=0;j<8;j++)
#pragma unroll
        for (int c=0;c<4;c++) oacc[j][c]=0.f;
    float l0 = 0.f, l1 = 0.f;

#pragma unroll 1
    for (int t = 0; t < 16; t++){
        if (t < 15){
            asm volatile("cp.async.wait_group 1;":::"memory");
        } else {
            asm volatile("cp.async.wait_group 0;":::"memory");
        }
        __syncthreads();
        if (t <= 13){
            int s2 = (t+2) % 3;
            KV_ISSUE((t+2)*64, s2);
            HK_GEN(t+2, s2);
        }
        const int scur = t % 3;

        const bf16* Qh = (const bf16*)(sp + O_QH);
        const bf16* Qm = (const bf16*)(sp + O_QM);
        const char* st = sp + O_KV + scur*KVSTG;
        const bf16* Kh = (const bf16*)(st + S_KH);
        const bf16* Km = (const bf16*)(st + S_KM);
        const bf16* Vh = (const bf16*)(st + S_VH);
        const bf16* Vm = (const bf16*)(st + S_VM);
        const float* Hc = (const float*)(sp + O_HK + scur*HKSTG);
        const float* Vc = (const float*)(sp + O_V1) + scur*64;

        float sacc[8][4];
#pragma unroll
        for (int j=0;j<8;j++)
#pragma unroll
            for (int c=0;c<4;c++) sacc[j][c]=0.f;
#pragma unroll
        for (int ks = 0; ks < 4; ks++){
            int kb = ks*16 + q2;
            uint32_t qa[4], qb[4];
            const bf16* p = Qh + rl0*72 + kb;
            qa[0]=*(const uint32_t*)p;     qa[1]=*(const uint32_t*)(p+8*72);
            qa[2]=*(const uint32_t*)(p+8); qa[3]=*(const uint32_t*)(p+8*72+8);
            const bf16* pm = Qm + rl0*72 + kb;
            qb[0]=*(const uint32_t*)pm;     qb[1]=*(const uint32_t*)(pm+8*72);
            qb[2]=*(const uint32_t*)(pm+8); qb[3]=*(const uint32_t*)(pm+8*72+8);
#pragma unroll
            for (int j = 0; j < 8; j++){
                const bf16* pk = Kh + (j*8 + ln4)*72 + kb;
                uint32_t bh0 = *(const uint32_t*)pk, bh1 = *(const uint32_t*)(pk+8);
                const bf16* pk2 = Km + (j*8 + ln4)*72 + kb;
                uint32_t bm0 = *(const uint32_t*)pk2, bm1 = *(const uint32_t*)(pk2+8);
                mma16816(sacc[j], qa, bh0, bh1);
                mma16816(sacc[j], qa, bm0, bm1);
                mma16816(sacc[j], qb, bh0, bh1);
            }
        }

        uint32_t pah[4][4], pam[4][4];
#pragma unroll
        for (int j = 0; j < 8; j++){
            float pe[4];
#pragma unroll
            for (int e = 0; e < 2; e++){
                int c = j*8 + q2 + e;
                const float4* hp = (const float4*)(Hc + c*20);
                float4 f0 = hp[0], f1 = hp[1], f2 = hp[2], f3 = hp[3];
                float hv[16] = {f0.x,f0.y,f0.z,f0.w, f1.x,f1.y,f1.z,f1.w,
                                f2.x,f2.y,f2.z,f2.w, f3.x,f3.y,f3.z,f3.w};
                float v1c = Vc[c];
                float s0 = sacc[j][e]   + U1r0 - v1c;
                float s1 = sacc[j][2+e] + U1r1 - v1c;
#pragma unroll
                for (int jj = 0; jj < 16; jj++){
                    s0 = fmaf(ws[jj], fabsf(uq0[jj] - hv[jj]), s0);
                    s1 = fmaf(ws[jj], fabsf(uq1[jj] - hv[jj]), s1);
                }
                float e0 = __expf(s0), e1 = __expf(s1);
                l0 += e0; l1 += e1;
                pe[e] = e0; pe[2+e] = e1;
            }
            int tt2 = j >> 1, base = (j & 1)*2;
            psplit2(pe[0], pe[1], pah[tt2][base],   pam[tt2][base]);
            psplit2(pe[2], pe[3], pah[tt2][base+1], pam[tt2][base+1]);
        }
#pragma unroll
        for (int tt = 0; tt < 4; tt++){
            int kb = tt*16 + q2;
#pragma unroll
            for (int j2 = 0; j2 < 8; j2++){
                const bf16* pv = Vh + (j2*8 + ln4)*72 + kb;
                uint32_t bh0 = *(const uint32_t*)pv, bh1 = *(const uint32_t*)(pv+8);
                const bf16* pv2 = Vm + (j2*8 + ln4)*72 + kb;
                uint32_t bm0 = *(const uint32_t*)pv2, bm1 = *(const uint32_t*)(pv2+8);
                mma16816(oacc[j2], pah[tt], bh0, bh1);
                mma16816(oacc[j2], pah[tt], bm0, bm1);
                mma16816(oacc[j2], pam[tt], bh0, bh1);
            }
        }
    }

    l0 += __shfl_xor_sync(0xffffffffu, l0, 1);
    l0 += __shfl_xor_sync(0xffffffffu, l0, 2);
    l1 += __shfl_xor_sync(0xffffffffu, l1, 1);
    l1 += __shfl_xor_sync(0xffffffffu, l1, 2);
    float inv0 = 1.f/l0, inv1 = 1.f/l1;
    size_t o0 = (size_t)(m*NQL + q0 + rl0)*DD + h*64;
    size_t o1 = o0 + 8*DD;
#pragma unroll
    for (int j2 = 0; j2 < 8; j2++){
        int c = j2*8 + q2;
        uint32_t hh, mm;
        psplit2(oacc[j2][0]*inv0, oacc[j2][1]*inv0, hh, mm);
        *(uint32_t*)(Cth + o0 + c) = hh; *(uint32_t*)(Ctm + o0 + c) = mm;
        psplit2(oacc[j2][2]*inv1, oacc[j2][3]*inv1, hh, mm);
        *(uint32_t*)(Cth + o1 + c) = hh; *(uint32_t*)(Ctm + o1 + c) = mm;
    }
}

// ---------------- host launcher ----------------
extern "C" void kernel_launch(void* const* d_in, const int* in_sizes, int n_in,
                              void* d_out, int out_size)
{
    const float* xq    = (const float*)d_in[0];
    const float* xk    = (const float*)d_in[1];
    const float* xv    = (const float*)d_in[2];
    const float* tq    = (const float*)d_in[3];
    const float* tk    = (const float*)d_in[4];
    const float* w_q   = (const float*)d_in[5];
    const float* w_k   = (const float*)d_in[6];
    const float* w_v   = (const float*)d_in[7];
    const float* w_out = (const float*)d_in[8];
    const float* b_out = (const float*)d_in[9];
    const float* kw1   = (const float*)d_in[10];
    const float* kb1   = (const float*)d_in[11];
    const float* kw2   = (const float*)d_in[12];
    const float* kb2   = (const float*)d_in[13];
    float* out = (float*)d_out;

    bf16 *xh,*xm,*wh,*wm,*qh,*qm,*kh,*km,*vth,*vtm,*cth,*ctm;
    float *vf;
    cudaGetSymbolAddress((void**)&xh,  g_xh);
    cudaGetSymbolAddress((void**)&xm,  g_xm);
    cudaGetSymbolAddress((void**)&wh,  g_wh);
    cudaGetSymbolAddress((void**)&wm,  g_wm);
    cudaGetSymbolAddress((void**)&qh,  g_qh);
    cudaGetSymbolAddress((void**)&qm,  g_qm);
    cudaGetSymbolAddress((void**)&kh,  g_kh);
    cudaGetSymbolAddress((void**)&km,  g_km);
    cudaGetSymbolAddress((void**)&vf,  g_vf);
    cudaGetSymbolAddress((void**)&vth, g_vth);
    cudaGetSymbolAddress((void**)&vtm, g_vtm);
    cudaGetSymbolAddress((void**)&cth, g_cth);
    cudaGetSymbolAddress((void**)&ctm, g_ctm);

    cudaFuncSetAttribute(qkv_proj, cudaFuncAttributeMaxDynamicSharedMemorySize, PJ_SMEM);
    cudaFuncSetAttribute(out_proj, cudaFuncAttributeMaxDynamicSharedMemorySize, PJ_SMEM);
    cudaFuncSetAttribute(attn_bf,  cudaFuncAttributeMaxDynamicSharedMemorySize, AT_SMEM);

    dim3 gx(N4/1024, 3);
    xsplit3<<<gx, 256>>>(xq, xk, xv, xh, xm);

    dim3 tg(16,16,4), tb(32,8);
    wtrans4<<<tg,tb>>>(w_q, w_k, w_v, w_out, wh, wm);

    dim3 gq(4, 64, 3);
    qkv_proj<<<gq,256,PJ_SMEM>>>(xh, xm, wh, wm, qh, qm, kh, km, vf);

    dim3 gv(32, 2, 64);
    vtrans<<<gv,tb>>>(vf, vth, vtm);

    dim3 ga(8, HH, MBN);
    attn_bf<<<ga,256,AT_SMEM>>>(qh, qm, kh, km, vth, vtm,
                                tq, tk, kw1, kb1, kw2, kb2, cth, ctm);

    dim3 go(4, 64);
    out_proj<<<go,256,PJ_SMEM>>>(cth, ctm, wh+3*(size_t)DD*DD, wm+3*(size_t)DD*DD,
                                 b_out, out);
}